// round 7
// baseline (speedup 1.0000x reference)
#include <cuda_runtime.h>
#include <cstdint>

// EGNNRegressor: fully fused per-graph pipeline (R6 resubmit — prior run died
// to a broker/container failure before executing; kernel re-audited, unchanged
// except comments).
//   grid = 1000 CTAs (one graph each), block = 384 threads (12 warps, 3/SMSP).
//   Rows padded 200->204 so every thread owns exactly 17 rows (row = ty + 12*r).
//   smem: x[204][128], Wfull[128][128] (whole layer, no tile syncs), pos, nbr.
//   GEMM: even/odd-k f32x2 partial accumulators -> zero dup-MOVs for h,
//         h is a broadcast LDS.128, W packed once per k-quad per chunk.
//   Aggregation goes through registers (hb buffer eliminated).

#define NGRAPH 1000
#define NPG    200
#define MD     128
#define NT     384
#define NWARP  12
#define NR     17          // rows per thread (204 padded rows / 12 warps)
#define RPAD   204

typedef unsigned long long ull;

__device__ __forceinline__ ull packff(float x, float y) {
    ull r;
    asm("mov.b64 %0, {%1, %2};" : "=l"(r) : "r"(__float_as_uint(x)), "r"(__float_as_uint(y)));
    return r;
}
__device__ __forceinline__ float2 unpf(ull v) {
    unsigned lo, hi;
    asm("mov.b64 {%0, %1}, %2;" : "=r"(lo), "=r"(hi) : "l"(v));
    return make_float2(__uint_as_float(lo), __uint_as_float(hi));
}
// packed fp32x2 FMA: d.xy += a.xy * b.xy  (SASS FFMA2 — 2x fp32 pipe rate)
__device__ __forceinline__ void ffma2(ull& d, ull a, ull b) {
    asm("fma.rn.f32x2 %0, %1, %2, %0;" : "+l"(d) : "l"(a), "l"(b));
}

// smem layout (floats):
//   xb : 204*128 = 26112 f   (104448 B)
//   wt : 128*128 = 16384 f   (65536 B)  — full W layer; reused as MLP scratch
//   px/py/pz : 3*204 = 612 f
//   nbr : 204*5 u8 (fits the +1024B tail)
#define XB_F   (RPAD * MD)
#define WT_F   (MD * MD)
#define SMEM_BYTES ((XB_F + WT_F + 3 * RPAD) * 4 + 1024)

// One row-chunk of the GEMM: RC rows x 4 cols per thread.
// acc lanes = (even-k partial, odd-k partial); combined + relu in epilogue.
template<int RC>
__device__ __forceinline__ void gemm_chunk(
    const float* __restrict__ xb, const float* __restrict__ wt,
    int ty, int tx, int rbase, float4 b4, float4* ov)
{
    const float4* wt4c = (const float4*)wt;
    ull acc[RC][4];
#pragma unroll
    for (int r = 0; r < RC; r++) {
        acc[r][0] = packff(b4.x, 0.0f);
        acc[r][1] = packff(b4.y, 0.0f);
        acc[r][2] = packff(b4.z, 0.0f);
        acc[r][3] = packff(b4.w, 0.0f);
    }
#pragma unroll 1
    for (int t = 0; t < 32; t++) {          // k-quad: k = 4t .. 4t+3
        float4 wa = wt4c[(4 * t + 0) * 32 + tx];
        float4 wb = wt4c[(4 * t + 1) * 32 + tx];
        float4 wc = wt4c[(4 * t + 2) * 32 + tx];
        float4 wd = wt4c[(4 * t + 3) * 32 + tx];
        ull w0a = packff(wa.x, wb.x), w1a = packff(wa.y, wb.y);
        ull w2a = packff(wa.z, wb.z), w3a = packff(wa.w, wb.w);
        ull w0b = packff(wc.x, wd.x), w1b = packff(wc.y, wd.y);
        ull w2b = packff(wc.z, wd.z), w3b = packff(wc.w, wd.w);
#pragma unroll
        for (int r = 0; r < RC; r++) {
            int row = ty + 12 * (rbase + r);
            // broadcast 16B load: (x[row][4t],x[row][4t+1]) , (x[row][4t+2],x[row][4t+3])
            ulonglong2 hv = *(const ulonglong2*)(xb + row * MD + 4 * t);
            ffma2(acc[r][0], hv.x, w0a);
            ffma2(acc[r][1], hv.x, w1a);
            ffma2(acc[r][2], hv.x, w2a);
            ffma2(acc[r][3], hv.x, w3a);
            ffma2(acc[r][0], hv.y, w0b);
            ffma2(acc[r][1], hv.y, w1b);
            ffma2(acc[r][2], hv.y, w2b);
            ffma2(acc[r][3], hv.y, w3b);
        }
    }
#pragma unroll
    for (int r = 0; r < RC; r++) {
        float2 p0 = unpf(acc[r][0]), p1 = unpf(acc[r][1]);
        float2 p2 = unpf(acc[r][2]), p3 = unpf(acc[r][3]);
        ov[rbase + r] = make_float4(fmaxf(p0.x + p0.y, 0.0f),
                                    fmaxf(p1.x + p1.y, 0.0f),
                                    fmaxf(p2.x + p2.y, 0.0f),
                                    fmaxf(p3.x + p3.y, 0.0f));
    }
}

__global__ void __launch_bounds__(NT, 1)
egnn_fused_kernel(const int* __restrict__ z, const float* __restrict__ pos,
                  const float* __restrict__ emb, const float* __restrict__ convW,
                  const float* __restrict__ convb,
                  const float* __restrict__ rW1, const float* __restrict__ rb1,
                  const float* __restrict__ rW2, const float* __restrict__ rb2,
                  const float* __restrict__ rW3, const float* __restrict__ rb3,
                  float* __restrict__ out)
{
    extern __shared__ float sm[];
    float* xb = sm;                        // 26112 f
    float* wt = xb + XB_F;                 // 16384 f
    float* px = wt + WT_F;
    float* py = px + RPAD;
    float* pz = py + RPAD;
    unsigned char* nbr = (unsigned char*)(pz + RPAD);

    const int g    = blockIdx.x;
    const int tid  = threadIdx.x;
    const int ty   = tid >> 5;             // 0..11
    const int tx   = tid & 31;             // 0..31
    const int base = g * NPG;

    float4*       xb4  = (float4*)xb;
    const float4* emb4 = (const float4*)emb;

    // ---- positions (SoA) ----
    for (int i = tid; i < NPG; i += NT) {
        px[i] = pos[(base + i) * 3 + 0];
        py[i] = pos[(base + i) * 3 + 1];
        pz[i] = pos[(base + i) * 3 + 2];
    }
    // ---- zero pad rows 200..203 (keeps pad lanes finite forever) ----
    if (tid < 128) {
        int pr = 200 + (tid >> 5);
        xb4[pr * 32 + (tid & 31)] = make_float4(0.f, 0.f, 0.f, 0.f);
    }
    if (tid < (RPAD - NPG) * 5) nbr[NPG * 5 + tid] = 0;   // pad nbr -> row 0
    // ---- gather embedding rows into xb ----
    for (int idx = tid; idx < NPG * 32; idx += NT) {
        int i = idx >> 5, c = idx & 31;
        xb4[i * 32 + c] = emb4[z[base + i] * 32 + c];
    }
    __syncthreads();

    // ---- KNN-5 (exclude self; strict-< insertion == top_k lower-index tie-break) ----
    if (tid < NPG) {
        const int i = tid;
        const float xi = px[i], yi = py[i], zi = pz[i];
        float bd[5] = {1e30f, 1e30f, 1e30f, 1e30f, 1e30f};
        int   bi[5] = {0, 0, 0, 0, 0};
        for (int j = 0; j < NPG; j++) {
            if (j == i) continue;
            float dx = xi - px[j], dy = yi - py[j], dz = zi - pz[j];
            float d2 = fmaf(dz, dz, fmaf(dy, dy, dx * dx));
            if (d2 < bd[4]) {
                if (d2 < bd[3]) {
                    bd[4] = bd[3]; bi[4] = bi[3];
                    if (d2 < bd[2]) {
                        bd[3] = bd[2]; bi[3] = bi[2];
                        if (d2 < bd[1]) {
                            bd[2] = bd[1]; bi[2] = bi[1];
                            if (d2 < bd[0]) {
                                bd[1] = bd[0]; bi[1] = bi[0];
                                bd[0] = d2; bi[0] = j;
                            } else { bd[1] = d2; bi[1] = j; }
                        } else { bd[2] = d2; bi[2] = j; }
                    } else { bd[3] = d2; bi[3] = j; }
                } else { bd[4] = d2; bi[4] = j; }
            }
        }
#pragma unroll
        for (int k = 0; k < 5; k++) nbr[i * 5 + k] = (unsigned char)bi[k];
    }
    __syncthreads();

    // ---- 3 GCN layers ----
    for (int l = 0; l < 3; l++) {
        // stage whole W[l] (64KB) into regs (L2-resident, MLP high) while
        // computing aggregation into regs (reads xb of previous layer).
        float4 wreg[11];
        const float4* Wl = (const float4*)convW + l * 4096;
#pragma unroll
        for (int q = 0; q < 11; q++) {
            int lin = q * NT + tid;
            float4 v = make_float4(0.f, 0.f, 0.f, 0.f);
            if (lin < 4096) v = Wl[lin];
            wreg[q] = v;
        }
        float4 areg[NR];
#pragma unroll
        for (int r = 0; r < NR; r++) {
            int row = ty + 12 * r;
            int n0 = nbr[row * 5 + 0], n1 = nbr[row * 5 + 1], n2 = nbr[row * 5 + 2];
            int n3 = nbr[row * 5 + 3], n4 = nbr[row * 5 + 4];
            float4 a = xb4[row * 32 + tx];
            float4 v;
            v = xb4[n0 * 32 + tx]; a.x += v.x; a.y += v.y; a.z += v.z; a.w += v.w;
            v = xb4[n1 * 32 + tx]; a.x += v.x; a.y += v.y; a.z += v.z; a.w += v.w;
            v = xb4[n2 * 32 + tx]; a.x += v.x; a.y += v.y; a.z += v.z; a.w += v.w;
            v = xb4[n3 * 32 + tx]; a.x += v.x; a.y += v.y; a.z += v.z; a.w += v.w;
            v = xb4[n4 * 32 + tx]; a.x += v.x; a.y += v.y; a.z += v.z; a.w += v.w;
            const float s = 1.0f / 6.0f;
            a.x *= s; a.y *= s; a.z *= s; a.w *= s;
            areg[r] = a;
        }
        __syncthreads();          // all agg reads of xb complete

        // commit W to smem + agg back into xb
#pragma unroll
        for (int q = 0; q < 11; q++) {
            int lin = q * NT + tid;
            if (lin < 4096) ((float4*)wt)[lin] = wreg[q];
        }
#pragma unroll
        for (int r = 0; r < NR; r++)
            xb4[(ty + 12 * r) * 32 + tx] = areg[r];
        __syncthreads();          // h (=xb) and W (=wt) ready

        // GEMM: relu(h @ W + b), 17 rows x 4 cols per thread, split 9+8
        float4 b4 = ((const float4*)(convb + l * MD))[tx];
        float4 ov[NR];
        gemm_chunk<9>(xb, wt, ty, tx, 0, b4, ov);
        gemm_chunk<8>(xb, wt, ty, tx, 9, b4, ov);
        __syncthreads();          // all GEMM reads of xb complete
#pragma unroll
        for (int r = 0; r < NR; r++)
            xb4[(ty + 12 * r) * 32 + tx] = ov[r];
        __syncthreads();          // layer output visible
    }

    // ---- mean pooling over 200 real rows -> wt[0..127] ----
    if (tid < MD) {
        float s = 0.0f;
        for (int i = 0; i < NPG; i++) s += xb[i * MD + tid];
        wt[tid] = s * (1.0f / 200.0f);
    }
    __syncthreads();

    // ---- regressor MLP 128->64->32->1 ----
    if (tid < 64) {
        float a = rb1[tid];
#pragma unroll 4
        for (int k = 0; k < 128; k++) a = fmaf(wt[k], rW1[k * 64 + tid], a);
        wt[128 + tid] = fmaxf(a, 0.0f);
    }
    __syncthreads();
    if (tid < 32) {
        float a = rb2[tid];
#pragma unroll 4
        for (int k = 0; k < 64; k++) a = fmaf(wt[128 + k], rW2[k * 32 + tid], a);
        wt[192 + tid] = fmaxf(a, 0.0f);
    }
    __syncthreads();
    if (tid == 0) {
        float a = rb3[0];
#pragma unroll
        for (int k = 0; k < 32; k++) a = fmaf(wt[192 + k], rW3[k], a);
        out[g] = a;
    }
}

extern "C" void kernel_launch(void* const* d_in, const int* in_sizes, int n_in,
                              void* d_out, int out_size)
{
    (void)in_sizes; (void)n_in; (void)out_size;
    const int*   z     = (const int*)  d_in[0];
    const float* pos   = (const float*)d_in[1];
    // d_in[2] = batch (unused: batch == node/200 by construction)
    const float* emb   = (const float*)d_in[3];
    const float* convW = (const float*)d_in[4];
    const float* convb = (const float*)d_in[5];
    const float* rW1   = (const float*)d_in[6];
    const float* rb1   = (const float*)d_in[7];
    const float* rW2   = (const float*)d_in[8];
    const float* rb2   = (const float*)d_in[9];
    const float* rW3   = (const float*)d_in[10];
    const float* rb3   = (const float*)d_in[11];
    float*       outp  = (float*)d_out;

    // idempotent, capture-safe (no stream op, no allocation)
    cudaFuncSetAttribute(egnn_fused_kernel,
                         cudaFuncAttributeMaxDynamicSharedMemorySize, SMEM_BYTES);

    egnn_fused_kernel<<<NGRAPH, NT, SMEM_BYTES>>>(
        z, pos, emb, convW, convb, rW1, rb1, rW2, rb2, rW3, rb3, outp);
}

// round 9
// speedup vs baseline: 1.3695x; 1.3695x over previous
#include <cuda_runtime.h>
#include <cstdint>

// EGNNRegressor R7 kernel, resubmitted verbatim (two broker "container failed
// twice" infra errors in a row; R6's identical failure mode ran fine on
// resubmit). Exact R5 structure (proven 710us, no spills) with ONE change:
// 256 -> 384 threads (12 warps, 3/SMSP) to lift the issue-utilization bound.
//   grid = 1000 CTAs (one graph each).
//   Rows padded 200->204; each thread owns 17 rows (row = ty + 12*r).
//   smem: x[204][128], h[204][128], Wtile[32][128], pos (SoA), nbr (u8).
// Per-thread GEMM registers DROP vs R5 (acc[17][2]=68 vs [25][2]=100) -> no
// spill risk (R6's regression was spill traffic from 44+68 regs live at once).

#define NGRAPH 1000
#define NPG    200
#define MD     128
#define NT     384
#define NR     17
#define RPAD   204

typedef unsigned long long ull;

__device__ __forceinline__ ull dupf(float x) {
    ull r; unsigned u = __float_as_uint(x);
    asm("mov.b64 %0, {%1, %1};" : "=l"(r) : "r"(u));
    return r;
}
__device__ __forceinline__ ull packff(float x, float y) {
    ull r;
    asm("mov.b64 %0, {%1, %2};" : "=l"(r) : "r"(__float_as_uint(x)), "r"(__float_as_uint(y)));
    return r;
}
__device__ __forceinline__ float2 unpf(ull v) {
    unsigned lo, hi;
    asm("mov.b64 {%0, %1}, %2;" : "=r"(lo), "=r"(hi) : "l"(v));
    return make_float2(__uint_as_float(lo), __uint_as_float(hi));
}
// packed fp32x2 FMA: d.xy += a.xy * b.xy  (SASS FFMA2 — 2x fp32 pipe rate)
__device__ __forceinline__ void ffma2(ull& d, ull a, ull b) {
    asm("fma.rn.f32x2 %0, %1, %2, %0;" : "+l"(d) : "l"(a), "l"(b));
}

// smem (floats): xb 204*128, hb 204*128, wt 32*128 (tile; MLP scratch),
// px/py/pz 3*204, nbr 204*5 u8 in the tail.
#define XB_F (RPAD * MD)
#define WT_F (32 * MD)
#define SMEM_BYTES ((XB_F + XB_F + WT_F + 3 * RPAD) * 4 + 1024)   // 228,752 B

__global__ void __launch_bounds__(NT, 1)
egnn_fused_kernel(const int* __restrict__ z, const float* __restrict__ pos,
                  const float* __restrict__ emb, const float* __restrict__ convW,
                  const float* __restrict__ convb,
                  const float* __restrict__ rW1, const float* __restrict__ rb1,
                  const float* __restrict__ rW2, const float* __restrict__ rb2,
                  const float* __restrict__ rW3, const float* __restrict__ rb3,
                  float* __restrict__ out)
{
    extern __shared__ float sm[];
    float* xb = sm;                       // 26112 f
    float* hb = xb + XB_F;                // 26112 f
    float* wt = hb + XB_F;                // 4096 f
    float* px = wt + WT_F;
    float* py = px + RPAD;
    float* pz = py + RPAD;
    unsigned char* nbr = (unsigned char*)(pz + RPAD);   // 1020 B in tail

    const int g    = blockIdx.x;
    const int tid  = threadIdx.x;
    const int ty   = tid >> 5;            // 0..11
    const int tx   = tid & 31;            // 0..31
    const int base = g * NPG;

    float4*       xb4  = (float4*)xb;
    float4*       hb4  = (float4*)hb;
    const float4* emb4 = (const float4*)emb;

    // ---- positions (SoA) ----
    for (int i = tid; i < NPG; i += NT) {
        px[i] = pos[(base + i) * 3 + 0];
        py[i] = pos[(base + i) * 3 + 1];
        pz[i] = pos[(base + i) * 3 + 2];
    }
    // ---- zero pad rows 200..203 of xb; pad nbr -> row 0 ----
    if (tid < 128) {
        int pr = 200 + (tid >> 5);
        xb4[pr * 32 + (tid & 31)] = make_float4(0.f, 0.f, 0.f, 0.f);
    }
    if (tid < (RPAD - NPG) * 5) nbr[NPG * 5 + tid] = 0;
    // ---- gather embedding rows into xb (coalesced, L2-resident table) ----
    for (int idx = tid; idx < NPG * 32; idx += NT) {
        int i = idx >> 5, c = idx & 31;
        xb4[i * 32 + c] = emb4[z[base + i] * 32 + c];
    }
    __syncthreads();

    // ---- KNN-5 (exclude self; strict-< insertion == top_k lower-index tie-break) ----
    if (tid < NPG) {
        const int i = tid;
        const float xi = px[i], yi = py[i], zi = pz[i];
        float bd[5] = {1e30f, 1e30f, 1e30f, 1e30f, 1e30f};
        int   bi[5] = {0, 0, 0, 0, 0};
        for (int j = 0; j < NPG; j++) {
            if (j == i) continue;
            float dx = xi - px[j], dy = yi - py[j], dz = zi - pz[j];
            float d2 = fmaf(dz, dz, fmaf(dy, dy, dx * dx));
            if (d2 < bd[4]) {
                if (d2 < bd[3]) {
                    bd[4] = bd[3]; bi[4] = bi[3];
                    if (d2 < bd[2]) {
                        bd[3] = bd[2]; bi[3] = bi[2];
                        if (d2 < bd[1]) {
                            bd[2] = bd[1]; bi[2] = bi[1];
                            if (d2 < bd[0]) {
                                bd[1] = bd[0]; bi[1] = bi[0];
                                bd[0] = d2; bi[0] = j;
                            } else { bd[1] = d2; bi[1] = j; }
                        } else { bd[2] = d2; bi[2] = j; }
                    } else { bd[3] = d2; bi[3] = j; }
                } else { bd[4] = d2; bi[4] = j; }
            }
        }
#pragma unroll
        for (int k = 0; k < 5; k++) nbr[i * 5 + k] = (unsigned char)bi[k];
    }

    // ---- 3 GCN layers (R5 structure) ----
    const float4* Wall4 = (const float4*)convW;
    const ull*    wt2   = (const ull*)wt;
    float4*       wt4   = (float4*)wt;

    for (int l = 0; l < 3; l++) {
        __syncthreads();   // nbr (l==0) / previous-layer xb stores visible

        // aggregation: hb[row] = (xb[row] + sum_k xb[nbr[row][k]]) / 6
#pragma unroll 1
        for (int r = 0; r < NR; r++) {
            int row = ty + 12 * r;
            int n0 = nbr[row * 5 + 0], n1 = nbr[row * 5 + 1], n2 = nbr[row * 5 + 2];
            int n3 = nbr[row * 5 + 3], n4 = nbr[row * 5 + 4];
            float4 a = xb4[row * 32 + tx];
            float4 v;
            v = xb4[n0 * 32 + tx]; a.x += v.x; a.y += v.y; a.z += v.z; a.w += v.w;
            v = xb4[n1 * 32 + tx]; a.x += v.x; a.y += v.y; a.z += v.z; a.w += v.w;
            v = xb4[n2 * 32 + tx]; a.x += v.x; a.y += v.y; a.z += v.z; a.w += v.w;
            v = xb4[n3 * 32 + tx]; a.x += v.x; a.y += v.y; a.z += v.z; a.w += v.w;
            v = xb4[n4 * 32 + tx]; a.x += v.x; a.y += v.y; a.z += v.z; a.w += v.w;
            const float s = 1.0f / 6.0f;
            a.x *= s; a.y *= s; a.z *= s; a.w *= s;
            hb4[row * 32 + tx] = a;
        }
        __syncthreads();   // hb ready; xb free for overwrite

        // GEMM: xb[i][j] = relu(b[j] + sum_k hb[i][k] * W[k][j])
        // thread tile: 17 rows (row = ty + 12*r) x 4 cols (j = 4tx..4tx+3)
        float4 b4 = ((const float4*)(convb + l * MD))[tx];
        ull acc[NR][2];
#pragma unroll
        for (int r = 0; r < NR; r++) {
            acc[r][0] = packff(b4.x, b4.y);
            acc[r][1] = packff(b4.z, b4.w);
        }

        for (int t = 0; t < 4; t++) {          // k tiles of 32
            __syncthreads();                   // previous tile fully consumed
            for (int lin = tid; lin < 1024; lin += NT)   // stage W[32t..][:] (16KB)
                wt4[lin] = Wall4[l * 4096 + t * 1024 + lin];
            __syncthreads();
#pragma unroll 1
            for (int kc = 0; kc < 8; kc++) {   // k sub-chunks of 4
                ull wp[4][2];
#pragma unroll
                for (int kk = 0; kk < 4; kk++) {
                    int idx = (kc * 4 + kk) * 64 + tx * 2;  // pairs (4tx,4tx+1),(4tx+2,4tx+3)
                    wp[kk][0] = wt2[idx];
                    wp[kk][1] = wt2[idx + 1];
                }
                int hcol = t * 8 + kc;
#pragma unroll
                for (int r = 0; r < NR; r++) {
                    float4 hv = hb4[(ty + 12 * r) * 32 + hcol]; // broadcast across warp
                    ull h0 = dupf(hv.x), h1 = dupf(hv.y), h2 = dupf(hv.z), h3 = dupf(hv.w);
                    ffma2(acc[r][0], h0, wp[0][0]); ffma2(acc[r][1], h0, wp[0][1]);
                    ffma2(acc[r][0], h1, wp[1][0]); ffma2(acc[r][1], h1, wp[1][1]);
                    ffma2(acc[r][0], h2, wp[2][0]); ffma2(acc[r][1], h2, wp[2][1]);
                    ffma2(acc[r][0], h3, wp[3][0]); ffma2(acc[r][1], h3, wp[3][1]);
                }
            }
        }
        // relu + store back to xb (safe: GEMM reads only hb/wt, next-layer
        // reads of xb are behind the loop-top barrier)
#pragma unroll
        for (int r = 0; r < NR; r++) {
            float2 p0 = unpf(acc[r][0]), p1 = unpf(acc[r][1]);
            float4 o;
            o.x = fmaxf(p0.x, 0.0f); o.y = fmaxf(p0.y, 0.0f);
            o.z = fmaxf(p1.x, 0.0f); o.w = fmaxf(p1.y, 0.0f);
            xb4[(ty + 12 * r) * 32 + tx] = o;
        }
    }
    __syncthreads();

    // ---- mean pooling over 200 real rows -> wt[0..127] ----
    if (tid < MD) {
        float s = 0.0f;
        for (int i = 0; i < NPG; i++) s += xb[i * MD + tid];
        wt[tid] = s * (1.0f / 200.0f);
    }
    __syncthreads();

    // ---- regressor MLP 128->64->32->1 ----
    if (tid < 64) {
        float a = rb1[tid];
#pragma unroll 4
        for (int k = 0; k < 128; k++) a = fmaf(wt[k], rW1[k * 64 + tid], a);
        wt[128 + tid] = fmaxf(a, 0.0f);
    }
    __syncthreads();
    if (tid < 32) {
        float a = rb2[tid];
#pragma unroll 4
        for (int k = 0; k < 64; k++) a = fmaf(wt[128 + k], rW2[k * 32 + tid], a);
        wt[192 + tid] = fmaxf(a, 0.0f);
    }
    __syncthreads();
    if (tid == 0) {
        float a = rb3[0];
#pragma unroll
        for (int k = 0; k < 32; k++) a = fmaf(wt[192 + k], rW3[k], a);
        out[g] = a;
    }
}

extern "C" void kernel_launch(void* const* d_in, const int* in_sizes, int n_in,
                              void* d_out, int out_size)
{
    (void)in_sizes; (void)n_in; (void)out_size;
    const int*   z     = (const int*)  d_in[0];
    const float* pos   = (const float*)d_in[1];
    // d_in[2] = batch (unused: batch == node/200 by construction)
    const float* emb   = (const float*)d_in[3];
    const float* convW = (const float*)d_in[4];
    const float* convb = (const float*)d_in[5];
    const float* rW1   = (const float*)d_in[6];
    const float* rb1   = (const float*)d_in[7];
    const float* rW2   = (const float*)d_in[8];
    const float* rb2   = (const float*)d_in[9];
    const float* rW3   = (const float*)d_in[10];
    const float* rb3   = (const float*)d_in[11];
    float*       outp  = (float*)d_out;

    // idempotent, capture-safe (no stream op, no allocation)
    cudaFuncSetAttribute(egnn_fused_kernel,
                         cudaFuncAttributeMaxDynamicSharedMemorySize, SMEM_BYTES);

    egnn_fused_kernel<<<NGRAPH, NT, SMEM_BYTES>>>(
        z, pos, emb, convW, convb, rW1, rb1, rW2, rb2, rW3, rb3, outp);
}

// round 13
// speedup vs baseline: 3.5010x; 2.5564x over previous
#include <cuda_runtime.h>
#include <cuda_bf16.h>
#include <cstdint>

// EGNNRegressor R12: fused per-graph pipeline with warp-level bf16 tensor-core
// GEMM (mma.sync.m16n8k16 — plain sm_103 PTX; tcgen05 is unavailable because
// the harness PTX targets sm_103 without the 'a' feature set).
//   grid = 1000 CTAs (one graph), block = 256 threads (8 warps).
//   X (features) fp32 in smem [208][128]. Aggregation writes H as TWO bf16
//   planes (hi/lo, x = hi+lo), row stride 136 bf16 = 272B (ldmatrix
//   conflict-free). GEMM: D = Hhi*Whi + Hhi*Wlo + Hlo*Whi, fp32 accum.
//   W fragments are precomputed into a __device__ global by a prep kernel
//   (bf16 hi/lo packed in mma B-fragment order) -> 16 coalesced LDG.128
//   per warp per layer, no runtime fragment shuffling.
//   Warp w owns output cols [16w,16w+16); 13 m-tiles (208 rows) in pairs.

#define NGRAPH 1000
#define NPG    200
#define MD     128
#define NT     256

// ---- smem map (bytes) ----
#define XB_OFF   0                       // 208*128 f32 = 106,496
#define HHI_OFF  106496                  // 208*272 = 56,576
#define HLO_OFF  163072                  // 56,576
#define PX_OFF   219648                  // 208 f
#define PY_OFF   (PX_OFF + 832)
#define PZ_OFF   (PY_OFF + 832)
#define SCR_OFF  (PZ_OFF + 832)          // 256 f scratch
#define NBR_OFF  (SCR_OFF + 1024)        // 208*5 u8 = 1040
#define SMEM_BYTES (NBR_OFF + 1040)      // 224,208 < 232,448

#define HSTRIDE 272                      // bytes per H row (136 bf16)

// W fragments: [layer][warp][blk(16)][lane(32)] uint4
// uint4 = regs (bhi0, bhi1, blo0, blo1) for (ks = blk>>1, nt = blk&1)
__device__ uint4 g_wfrag[3 * 8 * 16 * 32];

__device__ __forceinline__ uint32_t smem_u32(const void* p) {
    uint32_t a;
    asm("{ .reg .u64 t; cvta.to.shared.u64 t, %1; cvt.u32.u64 %0, t; }" : "=r"(a) : "l"(p));
    return a;
}
__device__ __forceinline__ void splitbf(float x, uint16_t& h, uint16_t& l) {
    __nv_bfloat16 hb = __float2bfloat16(x);
    __nv_bfloat16 lb = __float2bfloat16(x - __bfloat162float(hb));
    h = __bfloat16_as_ushort(hb);
    l = __bfloat16_as_ushort(lb);
}
#define LDM4(r, a) \
    asm volatile("ldmatrix.sync.aligned.m8n8.x4.shared.b16 {%0,%1,%2,%3}, [%4];" \
        : "=r"((r)[0]), "=r"((r)[1]), "=r"((r)[2]), "=r"((r)[3]) : "r"(a))

__device__ __forceinline__ void mma16816(float* c, const uint32_t* a,
                                         uint32_t b0, uint32_t b1) {
    asm volatile("mma.sync.aligned.m16n8k16.row.col.f32.bf16.bf16.f32 "
        "{%0,%1,%2,%3}, {%4,%5,%6,%7}, {%8,%9}, {%0,%1,%2,%3};"
        : "+f"(c[0]), "+f"(c[1]), "+f"(c[2]), "+f"(c[3])
        : "r"(a[0]), "r"(a[1]), "r"(a[2]), "r"(a[3]), "r"(b0), "r"(b1));
}

// ---- prep: pack W into mma B-fragment layout (bf16 hi/lo), once per launch ----
// B frag (m16n8k16 row.col): b0 = (k=2*(lane%4), n=lane/4) and (k+1, n);
// b1 = same with k+8. Here k also offsets by ks*16, n by w*16 + nt*8.
__global__ void egnn_wprep_kernel(const float* __restrict__ convW)
{
    int e = blockIdx.x * 256 + threadIdx.x;         // 12288 uint4 entries
    if (e >= 3 * 8 * 16 * 32) return;
    int lane = e & 31;
    int blk  = (e >> 5) & 15;
    int w    = (e >> 9) & 7;
    int l    = e >> 12;
    int ks = blk >> 1, nt = blk & 1;
    int n  = w * 16 + nt * 8 + (lane >> 2);
    uint32_t v[4];
#pragma unroll
    for (int q = 0; q < 4; q++) {
        int which = q & 1;                          // 0 -> b0 (k), 1 -> b1 (k+8)
        int split = (q >> 1) & 1;                   // 0 -> hi, 1 -> lo
        int k0 = ks * 16 + 2 * (lane & 3) + which * 8;
        float e0 = convW[l * MD * MD + k0 * MD + n];
        float e1 = convW[l * MD * MD + (k0 + 1) * MD + n];
        uint16_t h0, l0, h1, l1;
        splitbf(e0, h0, l0);
        splitbf(e1, h1, l1);
        uint16_t lo16 = split ? l0 : h0;
        uint16_t hi16 = split ? l1 : h1;
        v[q] = (uint32_t)lo16 | ((uint32_t)hi16 << 16);
    }
    g_wfrag[e] = make_uint4(v[0], v[1], v[2], v[3]);
}

__global__ void __launch_bounds__(NT, 1)
egnn_main_kernel(const int* __restrict__ z, const float* __restrict__ pos,
                 const float* __restrict__ emb, const float* __restrict__ convW,
                 const float* __restrict__ convb,
                 const float* __restrict__ rW1, const float* __restrict__ rb1,
                 const float* __restrict__ rW2, const float* __restrict__ rb2,
                 const float* __restrict__ rW3, const float* __restrict__ rb3,
                 float* __restrict__ out)
{
    extern __shared__ char smc[];
    float* xb  = (float*)(smc + XB_OFF);
    float* px  = (float*)(smc + PX_OFF);
    float* py  = (float*)(smc + PY_OFF);
    float* pz  = (float*)(smc + PZ_OFF);
    float* scr = (float*)(smc + SCR_OFF);
    unsigned char* nbr = (unsigned char*)(smc + NBR_OFF);

    const int g    = blockIdx.x;
    const int tid  = threadIdx.x;
    const int wid  = tid >> 5;               // 0..7
    const int lane = tid & 31;
    const int base = g * NPG;

    float4*       xb4  = (float4*)xb;
    const float4* emb4 = (const float4*)emb;

    // ---- positions ----
    for (int i = tid; i < NPG; i += NT) {
        px[i] = pos[(base + i) * 3 + 0];
        py[i] = pos[(base + i) * 3 + 1];
        pz[i] = pos[(base + i) * 3 + 2];
    }
    // ---- zero X pad rows 200..207 ----
    {
        int pr = 200 + (tid >> 5);           // 8 rows x 32 float4
        xb4[pr * 32 + lane] = make_float4(0.f, 0.f, 0.f, 0.f);
    }
    if (tid < 8 * 5) nbr[NPG * 5 + tid] = 0; // pad nbr -> row 0
    // ---- gather embeddings -> X fp32 ----
    for (int idx = tid; idx < NPG * 32; idx += NT) {
        int i = idx >> 5, c = idx & 31;
        xb4[i * 32 + c] = emb4[z[base + i] * 32 + c];
    }
    __syncthreads();

    // ---- KNN-5 (strict-< insertion == jax top_k lower-index tie-break) ----
    if (tid < NPG) {
        const int i = tid;
        const float xi = px[i], yi = py[i], zi = pz[i];
        float bd[5] = {1e30f, 1e30f, 1e30f, 1e30f, 1e30f};
        int   bi[5] = {0, 0, 0, 0, 0};
        for (int j = 0; j < NPG; j++) {
            if (j == i) continue;
            float dx = xi - px[j], dy = yi - py[j], dz = zi - pz[j];
            float d2 = fmaf(dz, dz, fmaf(dy, dy, dx * dx));
            if (d2 < bd[4]) {
                if (d2 < bd[3]) {
                    bd[4] = bd[3]; bi[4] = bi[3];
                    if (d2 < bd[2]) {
                        bd[3] = bd[2]; bi[3] = bi[2];
                        if (d2 < bd[1]) {
                            bd[2] = bd[1]; bi[2] = bi[1];
                            if (d2 < bd[0]) {
                                bd[1] = bd[0]; bi[1] = bi[0];
                                bd[0] = d2; bi[0] = j;
                            } else { bd[1] = d2; bi[1] = j; }
                        } else { bd[2] = d2; bi[2] = j; }
                    } else { bd[3] = d2; bi[3] = j; }
                } else { bd[4] = d2; bi[4] = j; }
            }
        }
#pragma unroll
        for (int k = 0; k < 5; k++) nbr[i * 5 + k] = (unsigned char)bi[k];
    }

    // ldmatrix per-lane base offset into an H plane (row lrow, col lcol)
    const int lrow = ((lane >> 3) & 1) * 8 + (lane & 7);
    const int lcol = ((lane >> 4) & 1) * 8;
    const uint32_t ldm_base = (uint32_t)(lrow * HSTRIDE + lcol * 2);
    const uint32_t sb_hhi = smem_u32(smc + HHI_OFF);
    const uint32_t sb_hlo = smem_u32(smc + HLO_OFF);

    // ---- 3 GCN layers ----
    for (int l = 0; l < 3; l++) {
        __syncthreads();   // nbr (l==0) / previous-layer X stores visible

        // B fragments for this layer (16 coalesced LDG.128) + bias
        uint4 breg[16];
        {
            const uint4* bp = g_wfrag + (l * 8 + wid) * 512 + lane;
#pragma unroll
            for (int blk = 0; blk < 16; blk++) breg[blk] = bp[blk * 32];
        }
        float bs[4];
        {
            int c0 = wid * 16 + 2 * (lane & 3);
            bs[0] = convb[l * MD + c0];
            bs[1] = convb[l * MD + c0 + 1];
            bs[2] = convb[l * MD + c0 + 8];
            bs[3] = convb[l * MD + c0 + 9];
        }

        // aggregation: H[row] = (X[row] + sum_5 X[nbr]) / 6, split -> planes
#pragma unroll 1
        for (int r = 0; r < 26; r++) {
            int row = wid + 8 * r;           // 0..207
            const unsigned char* nb = nbr + row * 5;
            int n0 = nb[0], n1 = nb[1], n2 = nb[2], n3 = nb[3], n4 = nb[4];
            float4 a = xb4[row * 32 + lane];
            float4 v;
            v = xb4[n0 * 32 + lane]; a.x += v.x; a.y += v.y; a.z += v.z; a.w += v.w;
            v = xb4[n1 * 32 + lane]; a.x += v.x; a.y += v.y; a.z += v.z; a.w += v.w;
            v = xb4[n2 * 32 + lane]; a.x += v.x; a.y += v.y; a.z += v.z; a.w += v.w;
            v = xb4[n3 * 32 + lane]; a.x += v.x; a.y += v.y; a.z += v.z; a.w += v.w;
            v = xb4[n4 * 32 + lane]; a.x += v.x; a.y += v.y; a.z += v.z; a.w += v.w;
            const float s = 1.0f / 6.0f;
            a.x *= s; a.y *= s; a.z *= s; a.w *= s;
            uint16_t h0, l0, h1, l1, h2, l2, h3, l3;
            splitbf(a.x, h0, l0); splitbf(a.y, h1, l1);
            splitbf(a.z, h2, l2); splitbf(a.w, h3, l3);
            uint32_t boff = (uint32_t)(row * HSTRIDE + lane * 8);
            *(ushort4*)(smc + HHI_OFF + boff) = make_ushort4(h0, h1, h2, h3);
            *(ushort4*)(smc + HLO_OFF + boff) = make_ushort4(l0, l1, l2, l3);
        }
        __syncthreads();   // H planes ready; X free for epilogue overwrite

        // GEMM: D[208 x 16-col slice] = H @ W, m-tiles in pairs for ILP
#pragma unroll 1
        for (int mp = 0; mp < 7; mp++) {
            int ma = 2 * mp, mb = 2 * mp + 1;
            bool hasb = (mb < 13);
            float acc[2][2][4];
#pragma unroll
            for (int t = 0; t < 2; t++)
#pragma unroll
                for (int nt = 0; nt < 2; nt++)
#pragma unroll
                    for (int q = 0; q < 4; q++) acc[t][nt][q] = 0.0f;

#pragma unroll
            for (int ks = 0; ks < 8; ks++) {
                uint32_t off_a = (uint32_t)(ma * 16 * HSTRIDE + ks * 32) + ldm_base;
                uint32_t Aha[4], Ala[4], Ahb[4], Alb[4];
                LDM4(Aha, sb_hhi + off_a);
                LDM4(Ala, sb_hlo + off_a);
                if (hasb) {
                    uint32_t off_b = off_a + (uint32_t)(16 * HSTRIDE);
                    LDM4(Ahb, sb_hhi + off_b);
                    LDM4(Alb, sb_hlo + off_b);
                }
#pragma unroll
                for (int nt = 0; nt < 2; nt++) {
                    uint4 B = breg[ks * 2 + nt];
                    mma16816(acc[0][nt], Aha, B.x, B.y);   // hi*hi
                    mma16816(acc[0][nt], Aha, B.z, B.w);   // hi*lo
                    mma16816(acc[0][nt], Ala, B.x, B.y);   // lo*hi
                    if (hasb) {
                        mma16816(acc[1][nt], Ahb, B.x, B.y);
                        mma16816(acc[1][nt], Ahb, B.z, B.w);
                        mma16816(acc[1][nt], Alb, B.x, B.y);
                    }
                }
            }
            // epilogue: relu(D + bias) -> X fp32
#pragma unroll
            for (int t = 0; t < 2; t++) {
                if (t == 1 && !hasb) break;
                int m = (t == 0) ? ma : mb;
                int r0 = 16 * m + (lane >> 2);
#pragma unroll
                for (int nt = 0; nt < 2; nt++) {
                    int col = wid * 16 + nt * 8 + 2 * (lane & 3);
                    float b0 = bs[nt * 2], b1 = bs[nt * 2 + 1];
                    float2 v0, v1;
                    v0.x = fmaxf(acc[t][nt][0] + b0, 0.0f);
                    v0.y = fmaxf(acc[t][nt][1] + b1, 0.0f);
                    v1.x = fmaxf(acc[t][nt][2] + b0, 0.0f);
                    v1.y = fmaxf(acc[t][nt][3] + b1, 0.0f);
                    *(float2*)(xb + r0 * MD + col)       = v0;
                    *(float2*)(xb + (r0 + 8) * MD + col) = v1;
                }
            }
        }
    }
    __syncthreads();

    // ---- mean pooling over 200 real rows -> scr[0..127] ----
    if (tid < MD) {
        float s = 0.0f;
        for (int row = 0; row < NPG; row++) s += xb[row * MD + tid];
        scr[tid] = s * (1.0f / 200.0f);
    }
    __syncthreads();

    // ---- regressor MLP 128->64->32->1 ----
    if (tid < 64) {
        float a = rb1[tid];
#pragma unroll 4
        for (int k = 0; k < 128; k++) a = fmaf(scr[k], rW1[k * 64 + tid], a);
        scr[128 + tid] = fmaxf(a, 0.0f);
    }
    __syncthreads();
    if (tid < 32) {
        float a = rb2[tid];
#pragma unroll 4
        for (int k = 0; k < 64; k++) a = fmaf(scr[128 + k], rW2[k * 32 + tid], a);
        scr[192 + tid] = fmaxf(a, 0.0f);
    }
    __syncthreads();
    if (tid == 0) {
        float a = rb3[0];
#pragma unroll
        for (int k = 0; k < 32; k++) a = fmaf(scr[192 + k], rW3[k], a);
        out[g] = a;
    }
}

extern "C" void kernel_launch(void* const* d_in, const int* in_sizes, int n_in,
                              void* d_out, int out_size)
{
    (void)in_sizes; (void)n_in; (void)out_size;
    const int*   z     = (const int*)  d_in[0];
    const float* pos   = (const float*)d_in[1];
    // d_in[2] = batch (unused: batch == node/200 by construction)
    const float* emb   = (const float*)d_in[3];
    const float* convW = (const float*)d_in[4];
    const float* convb = (const float*)d_in[5];
    const float* rW1   = (const float*)d_in[6];
    const float* rb1   = (const float*)d_in[7];
    const float* rW2   = (const float*)d_in[8];
    const float* rb2   = (const float*)d_in[9];
    const float* rW3   = (const float*)d_in[10];
    const float* rb3   = (const float*)d_in[11];
    float*       outp  = (float*)d_out;

    // idempotent, capture-safe (no stream op, no allocation)
    cudaFuncSetAttribute(egnn_main_kernel,
                         cudaFuncAttributeMaxDynamicSharedMemorySize, SMEM_BYTES);

    egnn_wprep_kernel<<<48, 256>>>(convW);
    egnn_main_kernel<<<NGRAPH, NT, SMEM_BYTES>>>(
        z, pos, emb, convW, convb, rW1, rb1, rW2, rb2, rW3, rb3, outp);
}

// round 14
// speedup vs baseline: 3.6337x; 1.0379x over previous
#include <cuda_runtime.h>
#include <cuda_bf16.h>
#include <cstdint>

// EGNNRegressor R13: warp-level bf16-split tensor-core pipeline (478us base)
// with stall-oriented fixes:
//   1) MMA terms reordered across 4 accumulator chains (reuse distance 4)
//   2) truncation bf16 split in aggregation (PRMT/LOP3 + cvt.rn.bf16x2)
//   3) nbr packed at stride 8 (one LDS.64 per row) + agg unroll 2
//   4) pooling parallelized 2x over 256 threads
//   grid = 1000 CTAs (one graph), block = 256 threads (8 warps).
//   X fp32 [208][128] in smem; H as hi/lo bf16 planes, row stride 272B;
//   D = Hhi*Whi + Hhi*Wlo + Hlo*Whi (fp32 accum, m16n8k16).
//   W fragments precomputed by prep kernel into __device__ global.

#define NGRAPH 1000
#define NPG    200
#define MD     128
#define NT     256

// ---- smem map (bytes) ----
#define XB_OFF   0                       // 208*128 f32 = 106,496
#define HHI_OFF  106496                  // 208*272 = 56,576
#define HLO_OFF  163072                  // 56,576
#define PX_OFF   219648                  // 208 f
#define PY_OFF   (PX_OFF + 832)
#define PZ_OFF   (PY_OFF + 832)
#define SCR_OFF  (PZ_OFF + 832)          // 384 f scratch (pool partials + mlp)
#define NBR_OFF  (SCR_OFF + 1536)        // 208*8 u8 = 1664
#define SMEM_BYTES (NBR_OFF + 1664)      // 225,344 < 232,448

#define HSTRIDE 272                      // bytes per H row (136 bf16)

// W fragments: [layer][warp][blk(16)][lane(32)] uint4
// uint4 = regs (bhi0, bhi1, blo0, blo1) for (ks = blk>>1, nt = blk&1)
__device__ uint4 g_wfrag[3 * 8 * 16 * 32];

__device__ __forceinline__ uint32_t smem_u32(const void* p) {
    uint32_t a;
    asm("{ .reg .u64 t; cvta.to.shared.u64 t, %1; cvt.u32.u64 %0, t; }" : "=r"(a) : "l"(p));
    return a;
}
__device__ __forceinline__ void splitbf_rn(float x, uint16_t& h, uint16_t& l) {
    __nv_bfloat16 hb = __float2bfloat16(x);
    __nv_bfloat16 lb = __float2bfloat16(x - __bfloat162float(hb));
    h = __bfloat16_as_ushort(hb);
    l = __bfloat16_as_ushort(lb);
}
#define LDM4(r, a) \
    asm volatile("ldmatrix.sync.aligned.m8n8.x4.shared.b16 {%0,%1,%2,%3}, [%4];" \
        : "=r"((r)[0]), "=r"((r)[1]), "=r"((r)[2]), "=r"((r)[3]) : "r"(a))

__device__ __forceinline__ void mma16816(float* c, const uint32_t* a,
                                         uint32_t b0, uint32_t b1) {
    asm volatile("mma.sync.aligned.m16n8k16.row.col.f32.bf16.bf16.f32 "
        "{%0,%1,%2,%3}, {%4,%5,%6,%7}, {%8,%9}, {%0,%1,%2,%3};"
        : "+f"(c[0]), "+f"(c[1]), "+f"(c[2]), "+f"(c[3])
        : "r"(a[0]), "r"(a[1]), "r"(a[2]), "r"(a[3]), "r"(b0), "r"(b1));
}

// ---- prep: pack W into mma B-fragment layout (bf16 hi/lo), once per launch ----
__global__ void egnn_wprep_kernel(const float* __restrict__ convW)
{
    int e = blockIdx.x * 256 + threadIdx.x;         // 12288 uint4 entries
    if (e >= 3 * 8 * 16 * 32) return;
    int lane = e & 31;
    int blk  = (e >> 5) & 15;
    int w    = (e >> 9) & 7;
    int l    = e >> 12;
    int ks = blk >> 1, nt = blk & 1;
    int n  = w * 16 + nt * 8 + (lane >> 2);
    uint32_t v[4];
#pragma unroll
    for (int q = 0; q < 4; q++) {
        int which = q & 1;                          // 0 -> b0 (k), 1 -> b1 (k+8)
        int split = (q >> 1) & 1;                   // 0 -> hi, 1 -> lo
        int k0 = ks * 16 + 2 * (lane & 3) + which * 8;
        float e0 = convW[l * MD * MD + k0 * MD + n];
        float e1 = convW[l * MD * MD + (k0 + 1) * MD + n];
        uint16_t h0, l0, h1, l1;
        splitbf_rn(e0, h0, l0);
        splitbf_rn(e1, h1, l1);
        uint16_t lo16 = split ? l0 : h0;
        uint16_t hi16 = split ? l1 : h1;
        v[q] = (uint32_t)lo16 | ((uint32_t)hi16 << 16);
    }
    g_wfrag[e] = make_uint4(v[0], v[1], v[2], v[3]);
}

__global__ void __launch_bounds__(NT, 1)
egnn_main_kernel(const int* __restrict__ z, const float* __restrict__ pos,
                 const float* __restrict__ emb, const float* __restrict__ convW,
                 const float* __restrict__ convb,
                 const float* __restrict__ rW1, const float* __restrict__ rb1,
                 const float* __restrict__ rW2, const float* __restrict__ rb2,
                 const float* __restrict__ rW3, const float* __restrict__ rb3,
                 float* __restrict__ out)
{
    extern __shared__ char smc[];
    float* xb  = (float*)(smc + XB_OFF);
    float* px  = (float*)(smc + PX_OFF);
    float* py  = (float*)(smc + PY_OFF);
    float* pz  = (float*)(smc + PZ_OFF);
    float* scr = (float*)(smc + SCR_OFF);
    unsigned char* nbr = (unsigned char*)(smc + NBR_OFF);

    const int g    = blockIdx.x;
    const int tid  = threadIdx.x;
    const int wid  = tid >> 5;               // 0..7
    const int lane = tid & 31;
    const int base = g * NPG;

    float4*       xb4  = (float4*)xb;
    const float4* emb4 = (const float4*)emb;

    // ---- positions ----
    for (int i = tid; i < NPG; i += NT) {
        px[i] = pos[(base + i) * 3 + 0];
        py[i] = pos[(base + i) * 3 + 1];
        pz[i] = pos[(base + i) * 3 + 2];
    }
    // ---- zero X pad rows 200..207; zero pad nbr ----
    {
        int pr = 200 + (tid >> 5);           // 8 rows x 32 float4
        xb4[pr * 32 + lane] = make_float4(0.f, 0.f, 0.f, 0.f);
    }
    if (tid < 8) *(uint2*)(nbr + (200 + tid) * 8) = make_uint2(0u, 0u);
    // ---- gather embeddings -> X fp32 ----
    for (int idx = tid; idx < NPG * 32; idx += NT) {
        int i = idx >> 5, c = idx & 31;
        xb4[i * 32 + c] = emb4[z[base + i] * 32 + c];
    }
    __syncthreads();

    // ---- KNN-5 (strict-< insertion == jax top_k lower-index tie-break) ----
    if (tid < NPG) {
        const int i = tid;
        const float xi = px[i], yi = py[i], zi = pz[i];
        float bd[5] = {1e30f, 1e30f, 1e30f, 1e30f, 1e30f};
        int   bi[5] = {0, 0, 0, 0, 0};
        for (int j = 0; j < NPG; j++) {
            if (j == i) continue;
            float dx = xi - px[j], dy = yi - py[j], dz = zi - pz[j];
            float d2 = fmaf(dz, dz, fmaf(dy, dy, dx * dx));
            if (d2 < bd[4]) {
                if (d2 < bd[3]) {
                    bd[4] = bd[3]; bi[4] = bi[3];
                    if (d2 < bd[2]) {
                        bd[3] = bd[2]; bi[3] = bi[2];
                        if (d2 < bd[1]) {
                            bd[2] = bd[1]; bi[2] = bi[1];
                            if (d2 < bd[0]) {
                                bd[1] = bd[0]; bi[1] = bi[0];
                                bd[0] = d2; bi[0] = j;
                            } else { bd[1] = d2; bi[1] = j; }
                        } else { bd[2] = d2; bi[2] = j; }
                    } else { bd[3] = d2; bi[3] = j; }
                } else { bd[4] = d2; bi[4] = j; }
            }
        }
        uint32_t w0 = (uint32_t)bi[0] | ((uint32_t)bi[1] << 8)
                    | ((uint32_t)bi[2] << 16) | ((uint32_t)bi[3] << 24);
        *(uint2*)(nbr + i * 8) = make_uint2(w0, (uint32_t)bi[4]);
    }

    // ldmatrix per-lane base offset into an H plane (row lrow, col lcol)
    const int lrow = ((lane >> 3) & 1) * 8 + (lane & 7);
    const int lcol = ((lane >> 4) & 1) * 8;
    const uint32_t ldm_base = (uint32_t)(lrow * HSTRIDE + lcol * 2);
    const uint32_t sb_hhi = smem_u32(smc + HHI_OFF);
    const uint32_t sb_hlo = smem_u32(smc + HLO_OFF);

    // ---- 3 GCN layers ----
    for (int l = 0; l < 3; l++) {
        __syncthreads();   // nbr (l==0) / previous-layer X stores visible

        // B fragments for this layer (16 coalesced LDG.128) + bias
        uint4 breg[16];
        {
            const uint4* bp = g_wfrag + (l * 8 + wid) * 512 + lane;
#pragma unroll
            for (int blk = 0; blk < 16; blk++) breg[blk] = bp[blk * 32];
        }
        float bs[4];
        {
            int c0 = wid * 16 + 2 * (lane & 3);
            bs[0] = convb[l * MD + c0];
            bs[1] = convb[l * MD + c0 + 1];
            bs[2] = convb[l * MD + c0 + 8];
            bs[3] = convb[l * MD + c0 + 9];
        }

        // aggregation: H[row] = (X[row] + sum_5 X[nbr]) / 6, trunc-split -> planes
#pragma unroll 2
        for (int r = 0; r < 26; r++) {
            int row = wid + 8 * r;           // 0..207
            uint2 nb8 = *(const uint2*)(nbr + row * 8);
            int n0 = nb8.x & 255, n1 = (nb8.x >> 8) & 255, n2 = (nb8.x >> 16) & 255;
            int n3 = nb8.x >> 24, n4 = nb8.y & 255;
            float4 a = xb4[row * 32 + lane];
            float4 v;
            v = xb4[n0 * 32 + lane]; a.x += v.x; a.y += v.y; a.z += v.z; a.w += v.w;
            v = xb4[n1 * 32 + lane]; a.x += v.x; a.y += v.y; a.z += v.z; a.w += v.w;
            v = xb4[n2 * 32 + lane]; a.x += v.x; a.y += v.y; a.z += v.z; a.w += v.w;
            v = xb4[n3 * 32 + lane]; a.x += v.x; a.y += v.y; a.z += v.z; a.w += v.w;
            v = xb4[n4 * 32 + lane]; a.x += v.x; a.y += v.y; a.z += v.z; a.w += v.w;
            const float s = 1.0f / 6.0f;
            a.x *= s; a.y *= s; a.z *= s; a.w *= s;
            // truncation split: hi = top16 bits (exact bf16), lo = rn(x - hi)
            uint32_t ax = __float_as_uint(a.x), ay = __float_as_uint(a.y);
            uint32_t az = __float_as_uint(a.z), aw = __float_as_uint(a.w);
            uint32_t hi01 = __byte_perm(ax, ay, 0x7632);   // (hix | hiy<<16)
            uint32_t hi23 = __byte_perm(az, aw, 0x7632);
            float lx = a.x - __uint_as_float(ax & 0xFFFF0000u);
            float ly = a.y - __uint_as_float(ay & 0xFFFF0000u);
            float lz = a.z - __uint_as_float(az & 0xFFFF0000u);
            float lw = a.w - __uint_as_float(aw & 0xFFFF0000u);
            uint32_t lo01, lo23;
            asm("cvt.rn.bf16x2.f32 %0, %1, %2;" : "=r"(lo01) : "f"(ly), "f"(lx));
            asm("cvt.rn.bf16x2.f32 %0, %1, %2;" : "=r"(lo23) : "f"(lw), "f"(lz));
            uint32_t boff = (uint32_t)(row * HSTRIDE + lane * 8);
            *(uint2*)(smc + HHI_OFF + boff) = make_uint2(hi01, hi23);
            *(uint2*)(smc + HLO_OFF + boff) = make_uint2(lo01, lo23);
        }
        __syncthreads();   // H planes ready; X free for epilogue overwrite

        // GEMM: D[208 x 16-col slice] = H @ W; terms rotated across 4 acc chains
#pragma unroll 1
        for (int mp = 0; mp < 7; mp++) {
            int ma = 2 * mp, mb = 2 * mp + 1;
            bool hasb = (mb < 13);
            float acc[2][2][4];
#pragma unroll
            for (int t = 0; t < 2; t++)
#pragma unroll
                for (int nt = 0; nt < 2; nt++)
#pragma unroll
                    for (int q = 0; q < 4; q++) acc[t][nt][q] = 0.0f;

#pragma unroll
            for (int ks = 0; ks < 8; ks++) {
                uint32_t off_a = (uint32_t)(ma * 16 * HSTRIDE + ks * 32) + ldm_base;
                uint32_t Aha[4], Ala[4], Ahb[4], Alb[4];
                LDM4(Aha, sb_hhi + off_a);
                LDM4(Ala, sb_hlo + off_a);
                if (hasb) {
                    uint32_t off_b = off_a + (uint32_t)(16 * HSTRIDE);
                    LDM4(Ahb, sb_hhi + off_b);
                    LDM4(Alb, sb_hlo + off_b);
                }
                uint4 B0 = breg[ks * 2 + 0];
                uint4 B1 = breg[ks * 2 + 1];
                // term s=0: hi*hi  (chains rotate: 00,01,10,11)
                mma16816(acc[0][0], Aha, B0.x, B0.y);
                mma16816(acc[0][1], Aha, B1.x, B1.y);
                if (hasb) {
                    mma16816(acc[1][0], Ahb, B0.x, B0.y);
                    mma16816(acc[1][1], Ahb, B1.x, B1.y);
                }
                // term s=1: hi*lo
                mma16816(acc[0][0], Aha, B0.z, B0.w);
                mma16816(acc[0][1], Aha, B1.z, B1.w);
                if (hasb) {
                    mma16816(acc[1][0], Ahb, B0.z, B0.w);
                    mma16816(acc[1][1], Ahb, B1.z, B1.w);
                }
                // term s=2: lo*hi
                mma16816(acc[0][0], Ala, B0.x, B0.y);
                mma16816(acc[0][1], Ala, B1.x, B1.y);
                if (hasb) {
                    mma16816(acc[1][0], Alb, B0.x, B0.y);
                    mma16816(acc[1][1], Alb, B1.x, B1.y);
                }
            }
            // epilogue: relu(D + bias) -> X fp32
#pragma unroll
            for (int t = 0; t < 2; t++) {
                if (t == 1 && !hasb) break;
                int m = (t == 0) ? ma : mb;
                int r0 = 16 * m + (lane >> 2);
#pragma unroll
                for (int nt = 0; nt < 2; nt++) {
                    int col = wid * 16 + nt * 8 + 2 * (lane & 3);
                    float b0 = bs[nt * 2], b1 = bs[nt * 2 + 1];
                    float2 v0, v1;
                    v0.x = fmaxf(acc[t][nt][0] + b0, 0.0f);
                    v0.y = fmaxf(acc[t][nt][1] + b1, 0.0f);
                    v1.x = fmaxf(acc[t][nt][2] + b0, 0.0f);
                    v1.y = fmaxf(acc[t][nt][3] + b1, 0.0f);
                    *(float2*)(xb + r0 * MD + col)       = v0;
                    *(float2*)(xb + (r0 + 8) * MD + col) = v1;
                }
            }
        }
    }
    __syncthreads();

    // ---- mean pooling over 200 real rows (2-way split over 256 threads) ----
    {
        int col  = tid & 127;
        int half = tid >> 7;                 // 0 or 1
        int r0   = half * 100;
        float s = 0.0f;
        for (int row = r0; row < r0 + 100; row++) s += xb[row * MD + col];
        scr[128 + tid] = s;                  // partials in scr[128..383]
    }
    __syncthreads();
    if (tid < 128)
        scr[tid] = (scr[128 + tid] + scr[256 + tid]) * (1.0f / 200.0f);
    __syncthreads();

    // ---- regressor MLP 128->64->32->1 ----
    if (tid < 64) {
        float a = rb1[tid];
#pragma unroll 4
        for (int k = 0; k < 128; k++) a = fmaf(scr[k], rW1[k * 64 + tid], a);
        scr[128 + tid] = fmaxf(a, 0.0f);
    }
    __syncthreads();
    if (tid < 32) {
        float a = rb2[tid];
#pragma unroll 4
        for (int k = 0; k < 64; k++) a = fmaf(scr[128 + k], rW2[k * 32 + tid], a);
        scr[192 + tid] = fmaxf(a, 0.0f);
    }
    __syncthreads();
    if (tid == 0) {
        float a = rb3[0];
#pragma unroll
        for (int k = 0; k < 32; k++) a = fmaf(scr[192 + k], rW3[k], a);
        out[g] = a;
    }
}

extern "C" void kernel_launch(void* const* d_in, const int* in_sizes, int n_in,
                              void* d_out, int out_size)
{
    (void)in_sizes; (void)n_in; (void)out_size;
    const int*   z     = (const int*)  d_in[0];
    const float* pos   = (const float*)d_in[1];
    // d_in[2] = batch (unused: batch == node/200 by construction)
    const float* emb   = (const float*)d_in[3];
    const float* convW = (const float*)d_in[4];
    const float* convb = (const float*)d_in[5];
    const float* rW1   = (const float*)d_in[6];
    const float* rb1   = (const float*)d_in[7];
    const float* rW2   = (const float*)d_in[8];
    const float* rb2   = (const float*)d_in[9];
    const float* rW3   = (const float*)d_in[10];
    const float* rb3   = (const float*)d_in[11];
    float*       outp  = (float*)d_out;

    // idempotent, capture-safe (no stream op, no allocation)
    cudaFuncSetAttribute(egnn_main_kernel,
                         cudaFuncAttributeMaxDynamicSharedMemorySize, SMEM_BYTES);

    egnn_wprep_kernel<<<48, 256>>>(convW);
    egnn_main_kernel<<<NGRAPH, NT, SMEM_BYTES>>>(
        z, pos, emb, convW, convb, rW1, rb1, rW2, rb2, rW3, rb3, outp);
}

// round 16
// speedup vs baseline: 3.8146x; 1.0498x over previous
#include <cuda_runtime.h>
#include <cuda_bf16.h>
#include <cstdint>

// EGNNRegressor R14 kernel, resubmitted verbatim: previous attempt died at
// harness device-init ("device busy or unavailable") before any kernel ran —
// infra, not kernel (4th such event; all prior resubmits ran fine).
//
// bf16-split mma.sync pipeline, 512 threads (16 warps, 4/SMSP) with M-split
// GEMM so total ldmatrix traffic is unchanged:
//   warp group A (wid<8): m-tiles 0-6, group B: m-tiles 7-12; each warp keeps
//   cols [16*(wid&7), +16)  -> A-fragments still amortized over 8 warps.
// X fp32 row stride 136 floats (544B = 32 mod 128) -> epilogue fragment
// stores hit the 2-phase crossbar minimum instead of 8-way conflicts.
// scr overlays the dead pos arrays to fit smem = 230,528 B.
// H planes / truncation split / packed nbr / W-fragment prep as in R13.

#define NGRAPH 1000
#define NPG    200
#define MD     128
#define NT     512
#define XSTR   136                       // X row stride in floats

// ---- smem map (bytes) ----
#define XB_OFF   0                       // 208*136*4 = 113,152
#define HHI_OFF  113152                  // 208*272 = 56,576
#define HLO_OFF  169728                  // 56,576
#define PX_OFF   226304                  // 208 f (dead after KNN)
#define PY_OFF   (PX_OFF + 832)
#define PZ_OFF   (PY_OFF + 832)
#define SCR_OFF  226304                  // overlays pos: 640 f (post-GEMM only)
#define NBR_OFF  228864                  // 208*8 u8 = 1664
#define SMEM_BYTES (NBR_OFF + 1664)      // 230,528 < 232,448

#define HSTRIDE 272                      // bytes per H row (136 bf16)

// W fragments: [layer][w8(8)][blk(16)][lane(32)] uint4
// uint4 = (bhi0, bhi1, blo0, blo1) for (ks = blk>>1, nt = blk&1)
__device__ uint4 g_wfrag[3 * 8 * 16 * 32];

__device__ __forceinline__ uint32_t smem_u32(const void* p) {
    uint32_t a;
    asm("{ .reg .u64 t; cvta.to.shared.u64 t, %1; cvt.u32.u64 %0, t; }" : "=r"(a) : "l"(p));
    return a;
}
__device__ __forceinline__ void splitbf_rn(float x, uint16_t& h, uint16_t& l) {
    __nv_bfloat16 hb = __float2bfloat16(x);
    __nv_bfloat16 lb = __float2bfloat16(x - __bfloat162float(hb));
    h = __bfloat16_as_ushort(hb);
    l = __bfloat16_as_ushort(lb);
}
#define LDM4(r, a) \
    asm volatile("ldmatrix.sync.aligned.m8n8.x4.shared.b16 {%0,%1,%2,%3}, [%4];" \
        : "=r"((r)[0]), "=r"((r)[1]), "=r"((r)[2]), "=r"((r)[3]) : "r"(a))

__device__ __forceinline__ void mma16816(float* c, const uint32_t* a,
                                         uint32_t b0, uint32_t b1) {
    asm volatile("mma.sync.aligned.m16n8k16.row.col.f32.bf16.bf16.f32 "
        "{%0,%1,%2,%3}, {%4,%5,%6,%7}, {%8,%9}, {%0,%1,%2,%3};"
        : "+f"(c[0]), "+f"(c[1]), "+f"(c[2]), "+f"(c[3])
        : "r"(a[0]), "r"(a[1]), "r"(a[2]), "r"(a[3]), "r"(b0), "r"(b1));
}

// ---- prep: pack W into mma B-fragment layout (bf16 hi/lo), once per launch ----
__global__ void egnn_wprep_kernel(const float* __restrict__ convW)
{
    int e = blockIdx.x * 256 + threadIdx.x;         // 12288 uint4 entries
    if (e >= 3 * 8 * 16 * 32) return;
    int lane = e & 31;
    int blk  = (e >> 5) & 15;
    int w    = (e >> 9) & 7;
    int l    = e >> 12;
    int ks = blk >> 1, nt = blk & 1;
    int n  = w * 16 + nt * 8 + (lane >> 2);
    uint32_t v[4];
#pragma unroll
    for (int q = 0; q < 4; q++) {
        int which = q & 1;                          // 0 -> b0 (k), 1 -> b1 (k+8)
        int split = (q >> 1) & 1;                   // 0 -> hi, 1 -> lo
        int k0 = ks * 16 + 2 * (lane & 3) + which * 8;
        float e0 = convW[l * MD * MD + k0 * MD + n];
        float e1 = convW[l * MD * MD + (k0 + 1) * MD + n];
        uint16_t h0, l0, h1, l1;
        splitbf_rn(e0, h0, l0);
        splitbf_rn(e1, h1, l1);
        uint16_t lo16 = split ? l0 : h0;
        uint16_t hi16 = split ? l1 : h1;
        v[q] = (uint32_t)lo16 | ((uint32_t)hi16 << 16);
    }
    g_wfrag[e] = make_uint4(v[0], v[1], v[2], v[3]);
}

__global__ void __launch_bounds__(NT, 1)
egnn_main_kernel(const int* __restrict__ z, const float* __restrict__ pos,
                 const float* __restrict__ emb, const float* __restrict__ convW,
                 const float* __restrict__ convb,
                 const float* __restrict__ rW1, const float* __restrict__ rb1,
                 const float* __restrict__ rW2, const float* __restrict__ rb2,
                 const float* __restrict__ rW3, const float* __restrict__ rb3,
                 float* __restrict__ out)
{
    extern __shared__ char smc[];
    float* xb  = (float*)(smc + XB_OFF);
    float* px  = (float*)(smc + PX_OFF);
    float* py  = (float*)(smc + PY_OFF);
    float* pz  = (float*)(smc + PZ_OFF);
    float* scr = (float*)(smc + SCR_OFF);
    unsigned char* nbr = (unsigned char*)(smc + NBR_OFF);

    const int g    = blockIdx.x;
    const int tid  = threadIdx.x;
    const int wid  = tid >> 5;               // 0..15
    const int lane = tid & 31;
    const int w8   = wid & 7;
    const int wg   = wid >> 3;               // 0: m 0-6, 1: m 7-12
    const int base = g * NPG;

    float4*       xb4  = (float4*)xb;        // row stride 34 float4
    const float4* emb4 = (const float4*)emb;

    // ---- positions ----
    for (int i = tid; i < NPG; i += NT) {
        px[i] = pos[(base + i) * 3 + 0];
        py[i] = pos[(base + i) * 3 + 1];
        pz[i] = pos[(base + i) * 3 + 2];
    }
    // ---- zero X pad rows 200..207 (all 34 float4 per row); pad nbr ----
    if (tid < 8 * 34) {
        int pr = 200 + tid / 34, c = tid % 34;
        xb4[pr * 34 + c] = make_float4(0.f, 0.f, 0.f, 0.f);
    }
    if (tid < 8) *(uint2*)(nbr + (200 + tid) * 8) = make_uint2(0u, 0u);
    // ---- gather embeddings -> X fp32 ----
    for (int idx = tid; idx < NPG * 32; idx += NT) {
        int i = idx >> 5, c = idx & 31;
        xb4[i * 34 + c] = emb4[z[base + i] * 32 + c];
    }
    __syncthreads();

    // ---- KNN-5 (strict-< insertion == jax top_k lower-index tie-break) ----
    if (tid < NPG) {
        const int i = tid;
        const float xi = px[i], yi = py[i], zi = pz[i];
        float bd[5] = {1e30f, 1e30f, 1e30f, 1e30f, 1e30f};
        int   bi[5] = {0, 0, 0, 0, 0};
        for (int j = 0; j < NPG; j++) {
            if (j == i) continue;
            float dx = xi - px[j], dy = yi - py[j], dz = zi - pz[j];
            float d2 = fmaf(dz, dz, fmaf(dy, dy, dx * dx));
            if (d2 < bd[4]) {
                if (d2 < bd[3]) {
                    bd[4] = bd[3]; bi[4] = bi[3];
                    if (d2 < bd[2]) {
                        bd[3] = bd[2]; bi[3] = bi[2];
                        if (d2 < bd[1]) {
                            bd[2] = bd[1]; bi[2] = bi[1];
                            if (d2 < bd[0]) {
                                bd[1] = bd[0]; bi[1] = bi[0];
                                bd[0] = d2; bi[0] = j;
                            } else { bd[1] = d2; bi[1] = j; }
                        } else { bd[2] = d2; bi[2] = j; }
                    } else { bd[3] = d2; bi[3] = j; }
                } else { bd[4] = d2; bi[4] = j; }
            }
        }
        uint32_t w0 = (uint32_t)bi[0] | ((uint32_t)bi[1] << 8)
                    | ((uint32_t)bi[2] << 16) | ((uint32_t)bi[3] << 24);
        *(uint2*)(nbr + i * 8) = make_uint2(w0, (uint32_t)bi[4]);
    }

    // ldmatrix per-lane base offset into an H plane
    const int lrow = ((lane >> 3) & 1) * 8 + (lane & 7);
    const int lcol = ((lane >> 4) & 1) * 8;
    const uint32_t ldm_base = (uint32_t)(lrow * HSTRIDE + lcol * 2);
    const uint32_t sb_hhi = smem_u32(smc + HHI_OFF);
    const uint32_t sb_hlo = smem_u32(smc + HLO_OFF);

    const int mstart = wg ? 7 : 0;
    const int mcount = wg ? 6 : 7;

    // ---- 3 GCN layers ----
    for (int l = 0; l < 3; l++) {
        __syncthreads();   // nbr (l==0) / previous-layer X stores visible

        // B fragments for this layer (16 coalesced LDG.128, shared by wg pair)
        uint4 breg[16];
        {
            const uint4* bp = g_wfrag + (l * 8 + w8) * 512 + lane;
#pragma unroll
            for (int blk = 0; blk < 16; blk++) breg[blk] = bp[blk * 32];
        }
        float bs[4];
        {
            int c0 = w8 * 16 + 2 * (lane & 3);
            bs[0] = convb[l * MD + c0];
            bs[1] = convb[l * MD + c0 + 1];
            bs[2] = convb[l * MD + c0 + 8];
            bs[3] = convb[l * MD + c0 + 9];
        }

        // aggregation: H[row] = (X[row] + sum_5 X[nbr]) / 6, trunc-split
#pragma unroll 2
        for (int r = 0; r < 13; r++) {
            int row = wid + 16 * r;          // 0..207
            uint2 nb8 = *(const uint2*)(nbr + row * 8);
            int n0 = nb8.x & 255, n1 = (nb8.x >> 8) & 255, n2 = (nb8.x >> 16) & 255;
            int n3 = nb8.x >> 24, n4 = nb8.y & 255;
            float4 a = xb4[row * 34 + lane];
            float4 v;
            v = xb4[n0 * 34 + lane]; a.x += v.x; a.y += v.y; a.z += v.z; a.w += v.w;
            v = xb4[n1 * 34 + lane]; a.x += v.x; a.y += v.y; a.z += v.z; a.w += v.w;
            v = xb4[n2 * 34 + lane]; a.x += v.x; a.y += v.y; a.z += v.z; a.w += v.w;
            v = xb4[n3 * 34 + lane]; a.x += v.x; a.y += v.y; a.z += v.z; a.w += v.w;
            v = xb4[n4 * 34 + lane]; a.x += v.x; a.y += v.y; a.z += v.z; a.w += v.w;
            const float s = 1.0f / 6.0f;
            a.x *= s; a.y *= s; a.z *= s; a.w *= s;
            // truncation split: hi = top16 bits (exact bf16), lo = rn(x - hi)
            uint32_t ax = __float_as_uint(a.x), ay = __float_as_uint(a.y);
            uint32_t az = __float_as_uint(a.z), aw = __float_as_uint(a.w);
            uint32_t hi01 = __byte_perm(ax, ay, 0x7632);
            uint32_t hi23 = __byte_perm(az, aw, 0x7632);
            float lx = a.x - __uint_as_float(ax & 0xFFFF0000u);
            float ly = a.y - __uint_as_float(ay & 0xFFFF0000u);
            float lz = a.z - __uint_as_float(az & 0xFFFF0000u);
            float lw = a.w - __uint_as_float(aw & 0xFFFF0000u);
            uint32_t lo01, lo23;
            asm("cvt.rn.bf16x2.f32 %0, %1, %2;" : "=r"(lo01) : "f"(ly), "f"(lx));
            asm("cvt.rn.bf16x2.f32 %0, %1, %2;" : "=r"(lo23) : "f"(lw), "f"(lz));
            uint32_t boff = (uint32_t)(row * HSTRIDE + lane * 8);
            *(uint2*)(smc + HHI_OFF + boff) = make_uint2(hi01, hi23);
            *(uint2*)(smc + HLO_OFF + boff) = make_uint2(lo01, lo23);
        }
        __syncthreads();   // H planes ready; X free for epilogue overwrite

        // GEMM: warp (wg,w8) computes m-tiles [mstart,mstart+mcount) x 16 cols
#pragma unroll 1
        for (int mi = 0; mi < mcount; mi++) {
            int m = mstart + mi;
            float acc[2][4];
#pragma unroll
            for (int nt = 0; nt < 2; nt++)
#pragma unroll
                for (int q = 0; q < 4; q++) acc[nt][q] = 0.0f;

#pragma unroll
            for (int ks = 0; ks < 8; ks++) {
                uint32_t off_a = (uint32_t)(m * 16 * HSTRIDE + ks * 32) + ldm_base;
                uint32_t Ah[4], Al[4];
                LDM4(Ah, sb_hhi + off_a);
                LDM4(Al, sb_hlo + off_a);
                uint4 B0 = breg[ks * 2 + 0];
                uint4 B1 = breg[ks * 2 + 1];
                mma16816(acc[0], Ah, B0.x, B0.y);   // hi*hi nt0
                mma16816(acc[1], Ah, B1.x, B1.y);   // hi*hi nt1
                mma16816(acc[0], Ah, B0.z, B0.w);   // hi*lo nt0
                mma16816(acc[1], Ah, B1.z, B1.w);   // hi*lo nt1
                mma16816(acc[0], Al, B0.x, B0.y);   // lo*hi nt0
                mma16816(acc[1], Al, B1.x, B1.y);   // lo*hi nt1
            }
            // epilogue: relu(D + bias) -> X fp32 (stride 136: 2-phase stores)
            int r0 = 16 * m + (lane >> 2);
#pragma unroll
            for (int nt = 0; nt < 2; nt++) {
                int col = w8 * 16 + nt * 8 + 2 * (lane & 3);
                float b0 = bs[nt * 2], b1 = bs[nt * 2 + 1];
                float2 v0, v1;
                v0.x = fmaxf(acc[nt][0] + b0, 0.0f);
                v0.y = fmaxf(acc[nt][1] + b1, 0.0f);
                v1.x = fmaxf(acc[nt][2] + b0, 0.0f);
                v1.y = fmaxf(acc[nt][3] + b1, 0.0f);
                *(float2*)(xb + r0 * XSTR + col)       = v0;
                *(float2*)(xb + (r0 + 8) * XSTR + col) = v1;
            }
        }
    }
    __syncthreads();

    // ---- mean pooling over 200 real rows (4-way split over 512 threads) ----
    {
        int col = tid & 127;
        int q   = tid >> 7;                  // 0..3
        int r0  = q * 50;
        float s = 0.0f;
        for (int row = r0; row < r0 + 50; row++) s += xb[row * XSTR + col];
        scr[128 + tid] = s;                  // partials scr[128..639]
    }
    __syncthreads();
    if (tid < 128)
        scr[tid] = (scr[128 + tid] + scr[256 + tid] + scr[384 + tid]
                  + scr[512 + tid]) * (1.0f / 200.0f);
    __syncthreads();

    // ---- regressor MLP 128->64->32->1 ----
    if (tid < 64) {
        float a = rb1[tid];
#pragma unroll 4
        for (int k = 0; k < 128; k++) a = fmaf(scr[k], rW1[k * 64 + tid], a);
        scr[128 + tid] = fmaxf(a, 0.0f);
    }
    __syncthreads();
    if (tid < 32) {
        float a = rb2[tid];
#pragma unroll 4
        for (int k = 0; k < 64; k++) a = fmaf(scr[128 + k], rW2[k * 32 + tid], a);
        scr[192 + tid] = fmaxf(a, 0.0f);
    }
    __syncthreads();
    if (tid == 0) {
        float a = rb3[0];
#pragma unroll
        for (int k = 0; k < 32; k++) a = fmaf(scr[192 + k], rW3[k], a);
        out[g] = a;
    }
}

extern "C" void kernel_launch(void* const* d_in, const int* in_sizes, int n_in,
                              void* d_out, int out_size)
{
    (void)in_sizes; (void)n_in; (void)out_size;
    const int*   z     = (const int*)  d_in[0];
    const float* pos   = (const float*)d_in[1];
    // d_in[2] = batch (unused: batch == node/200 by construction)
    const float* emb   = (const float*)d_in[3];
    const float* convW = (const float*)d_in[4];
    const float* convb = (const float*)d_in[5];
    const float* rW1   = (const float*)d_in[6];
    const float* rb1   = (const float*)d_in[7];
    const float* rW2   = (const float*)d_in[8];
    const float* rb2   = (const float*)d_in[9];
    const float* rW3   = (const float*)d_in[10];
    const float* rb3   = (const float*)d_in[11];
    float*       outp  = (float*)d_out;

    // idempotent, capture-safe (no stream op, no allocation)
    cudaFuncSetAttribute(egnn_main_kernel,
                         cudaFuncAttributeMaxDynamicSharedMemorySize, SMEM_BYTES);

    egnn_wprep_kernel<<<48, 256>>>(convW);
    egnn_main_kernel<<<NGRAPH, NT, SMEM_BYTES>>>(
        z, pos, emb, convW, convb, rW1, rb1, rW2, rb2, rW3, rb3, outp);
}